// round 3
// baseline (speedup 1.0000x reference)
#include <cuda_runtime.h>
#include <cuda_fp16.h>
#include <cstdint>

// ---------------------------------------------------------------------------
// XORConv2d: out = conv_valid(x, 1-2W), x (32,128,64,64) f32, W (256,128,3,3)
// Implicit GEMM on mma.sync (HMMA) fp16 / fp32 accum. Target is plain sm_103
// (no 'a' features: no tcgen05/TMEM). cp.async + ldmatrix + mma.sync only.
// ---------------------------------------------------------------------------

#define BDIM   32
#define CIN    128
#define HH     64
#define WWID   64
#define COUT   256
#define HOUT   62
#define WOUT   62
#define PIX_PER_IMG (HOUT*WOUT)         // 3844
#define NPIX  (BDIM*PIX_PER_IMG)        // 123008 = 961 * 128

// Scratch: x in NHWC fp16 (contiguous channels -> vectorized im2col loads)
__device__ __half g_x[(size_t)BDIM * HH * WWID * CIN];   // 32 MB
// Effective weights (1-2W) fp16, layout [kpos(9)][co(256)][cin(128)]
__device__ __half g_w[9 * COUT * CIN];

static __device__ __forceinline__ uint32_t smem_u32(const void* p) {
    uint32_t a;
    asm("{ .reg .u64 t; cvta.to.shared.u64 t, %1; cvt.u32.u64 %0, t; }"
        : "=r"(a) : "l"(p));
    return a;
}

// ---------------------------------------------------------------------------
// Prep 1: x NCHW fp32 -> NHWC fp16 (tiled transpose through smem)
// grid (BDIM*HH, CIN/32, WWID/32), 256 threads
// ---------------------------------------------------------------------------
__global__ void x_to_nhwc(const float* __restrict__ x) {
    __shared__ float t[32][33];
    int bh = blockIdx.x;               // b*64 + h
    int b  = bh >> 6, h = bh & 63;
    int c0 = blockIdx.y * 32;
    int w0 = blockIdx.z * 32;
    int tx = threadIdx.x & 31, ty = threadIdx.x >> 5;   // ty 0..7

    const float* src = x + ((size_t)(b * CIN + c0)) * (HH * WWID) + h * WWID + w0;
#pragma unroll
    for (int i = 0; i < 4; i++)
        t[ty + 8 * i][tx] = src[(size_t)(ty + 8 * i) * (HH * WWID) + tx];
    __syncthreads();

    __half* dst = g_x + ((size_t)bh * WWID + w0) * CIN + c0;
#pragma unroll
    for (int i = 0; i < 4; i++)
        dst[(size_t)(ty + 8 * i) * CIN + tx] = __float2half_rn(t[tx][ty + 8 * i]);
}

// ---------------------------------------------------------------------------
// Prep 2: W (co,cin,kh,kw) f32 {0,1} -> g_w[kpos][co][cin] = 1-2W (fp16)
// ---------------------------------------------------------------------------
__global__ void w_prep(const float* __restrict__ W) {
    int idx = blockIdx.x * 256 + threadIdx.x;
    if (idx < COUT * CIN * 9) {
        int co  = idx / (CIN * 9);
        int r   = idx - co * (CIN * 9);
        int cin = r / 9;
        int kp  = r - cin * 9;
        g_w[(kp * COUT + co) * CIN + cin] = __float2half_rn(1.0f - 2.0f * W[idx]);
    }
}

// ---------------------------------------------------------------------------
// Main: CTA = 128 co x 128 pixels. 9 kpos iterations of K=128.
// Double-buffered cp.async, XOR-swizzled smem, ldmatrix + mma.sync.m16n8k16.
// 8 warps: 4(M) x 2(N); warp tile 32(M) x 64(N).
// grid (961, 2), 256 threads.
// ---------------------------------------------------------------------------
#define STAGE      65536          // 32KB A + 32KB B per stage
#define SMEM_BYTES (2*STAGE)

__global__ void __launch_bounds__(256, 1)
xorconv_main(float* __restrict__ out) {
    extern __shared__ char smem[];
    const uint32_t sb = smem_u32(smem);

    const int tid     = threadIdx.x;
    const int l       = tid & 31;
    const int w       = tid >> 5;
    const int P0      = blockIdx.x * 128;   // first flat pixel of tile
    const int co_base = blockIdx.y * 128;

    // ----- global->shared load mapping: thread = (chunk c, row-group rgrp)
    const int c    = tid & 15;     // 16B chunk within a 256B row
    const int rgrp = tid >> 4;     // 16 row groups, rows r = rgrp + 16*i
    uint32_t rbv[8];
#pragma unroll
    for (int i = 0; i < 8; i++) {
        int pg  = P0 + rgrp + 16 * i;
        int b   = pg / PIX_PER_IMG;
        int rem = pg - b * PIX_PER_IMG;
        int ho  = rem / WOUT;
        int wo  = rem - ho * WOUT;
        rbv[i] = (uint32_t)(((b * HH + ho) * WWID + wo) * CIN);
    }

    auto load_stage = [&](int s, int kp) {
        uint32_t dA = sb + s * STAGE;
        uint32_t dB = dA + 32768;
        const __half* wp = g_w + (kp * COUT + co_base) * CIN;
        int kh = kp / 3, kw = kp - 3 * kh;
        uint32_t koff = (uint32_t)((kh * WWID + kw) * CIN);
#pragma unroll
        for (int i = 0; i < 8; i++) {
            int r = rgrp + 16 * i;
            uint32_t sw = (uint32_t)r * 256u + (uint32_t)((c ^ (r & 7)) * 16);
            const __half* gA = wp + r * CIN + c * 8;
            const __half* gB = g_x + rbv[i] + koff + c * 8;
            asm volatile(
                "cp.async.cg.shared.global [%0], [%1], 16;\n\t"
                "cp.async.cg.shared.global [%2], [%3], 16;"
                :: "r"(dA + sw), "l"(gA), "r"(dB + sw), "l"(gB));
        }
        asm volatile("cp.async.commit_group;" ::: "memory");
    };

    load_stage(0, 0);

    const int wm = w & 3;           // M group (32 rows)
    const int wn = w >> 2;          // N group (64 cols)
    float acc[2][8][4];
#pragma unroll
    for (int a = 0; a < 2; a++)
#pragma unroll
        for (int b = 0; b < 8; b++)
#pragma unroll
            for (int e = 0; e < 4; e++) acc[a][b][e] = 0.f;

    const int rowA0 = wm * 32 + (l & 15);
    const int rowB0 = wn * 64 + (l & 7) + ((l >> 4) << 3);
    const uint32_t selA = (uint32_t)(l >> 4);        // A chunk low bit
    const uint32_t selB = (uint32_t)((l >> 3) & 1);  // B chunk low bit

    for (int kp = 0; kp < 9; kp++) {
        if (kp < 8) {
            load_stage((kp + 1) & 1, kp + 1);
            asm volatile("cp.async.wait_group 1;" ::: "memory");
        } else {
            asm volatile("cp.async.wait_group 0;" ::: "memory");
        }
        __syncthreads();

        uint32_t A = sb + (kp & 1) * STAGE;
        uint32_t B = A + 32768;
#pragma unroll
        for (int j = 0; j < 8; j++) {           // K=128 in 8 x k16
            uint32_t a[2][4], bq[4][4];
#pragma unroll
            for (int fm = 0; fm < 2; fm++) {
                int r = rowA0 + fm * 16;
                uint32_t ch = ((uint32_t)(2 * j) + selA) ^ (uint32_t)(r & 7);
                uint32_t ad = A + (uint32_t)r * 256u + ch * 16u;
                asm volatile(
                    "ldmatrix.sync.aligned.m8n8.x4.shared.b16 {%0,%1,%2,%3}, [%4];"
                    : "=r"(a[fm][0]), "=r"(a[fm][1]), "=r"(a[fm][2]), "=r"(a[fm][3])
                    : "r"(ad));
            }
#pragma unroll
            for (int nb = 0; nb < 4; nb++) {
                int r = rowB0 + nb * 16;
                uint32_t ch = ((uint32_t)(2 * j) + selB) ^ (uint32_t)(r & 7);
                uint32_t ad = B + (uint32_t)r * 256u + ch * 16u;
                asm volatile(
                    "ldmatrix.sync.aligned.m8n8.x4.shared.b16 {%0,%1,%2,%3}, [%4];"
                    : "=r"(bq[nb][0]), "=r"(bq[nb][1]), "=r"(bq[nb][2]), "=r"(bq[nb][3])
                    : "r"(ad));
            }
#pragma unroll
            for (int fm = 0; fm < 2; fm++)
#pragma unroll
                for (int nf = 0; nf < 8; nf++) {
                    asm volatile(
                        "mma.sync.aligned.m16n8k16.row.col.f32.f16.f16.f32 "
                        "{%0,%1,%2,%3}, {%4,%5,%6,%7}, {%8,%9}, {%0,%1,%2,%3};"
                        : "+f"(acc[fm][nf][0]), "+f"(acc[fm][nf][1]),
                          "+f"(acc[fm][nf][2]), "+f"(acc[fm][nf][3])
                        : "r"(a[fm][0]), "r"(a[fm][1]), "r"(a[fm][2]), "r"(a[fm][3]),
                          "r"(bq[nf >> 1][(nf & 1) * 2]),
                          "r"(bq[nf >> 1][(nf & 1) * 2 + 1]));
                }
        }
        __syncthreads();   // stage consumed before next-next loads overwrite it
    }

    // ----- epilogue: direct NCHW fp32 stores from accumulators
#pragma unroll
    for (int fm = 0; fm < 2; fm++) {
        int m = co_base + wm * 32 + fm * 16 + (l >> 2);
#pragma unroll
        for (int nf = 0; nf < 8; nf++) {
            int pg = P0 + wn * 64 + nf * 8 + (l & 3) * 2;
#pragma unroll
            for (int e = 0; e < 2; e++) {
                int p   = pg + e;
                int b   = p / PIX_PER_IMG;
                int rem = p - b * PIX_PER_IMG;
                size_t base = (size_t)(b * COUT + m) * PIX_PER_IMG + rem;
                out[base]                            = acc[fm][nf][e];
                out[base + (size_t)8 * PIX_PER_IMG]  = acc[fm][nf][2 + e];
            }
        }
    }
}

// ---------------------------------------------------------------------------
extern "C" void kernel_launch(void* const* d_in, const int* in_sizes, int n_in,
                              void* d_out, int out_size) {
    const float* x = (const float*)d_in[0];
    const float* W = (const float*)d_in[1];
    float* out = (float*)d_out;

    dim3 gt(BDIM * HH, CIN / 32, WWID / 32);
    x_to_nhwc<<<gt, 256>>>(x);
    w_prep<<<(COUT * CIN * 9 + 255) / 256, 256>>>(W);

    cudaFuncSetAttribute(xorconv_main,
                         cudaFuncAttributeMaxDynamicSharedMemorySize, SMEM_BYTES);
    dim3 gm(NPIX / 128, 2);
    xorconv_main<<<gm, 256, SMEM_BYTES>>>(out);
}

// round 4
// speedup vs baseline: 1.5681x; 1.5681x over previous
#include <cuda_runtime.h>
#include <cuda_fp16.h>
#include <cstdint>

// ---------------------------------------------------------------------------
// XORConv2d: out = conv_valid(x, 1-2W), x (32,128,64,64) f32, W (256,128,3,3)
// Implicit GEMM on mma.sync fp16/fp32. sm_103 plain target (no tcgen05).
// R4: 256(co) x 124(pix) CTA tile; B comes from a 64KB input-row patch loaded
// ONCE per CTA (9x less B traffic); 512 threads, 16 warps (4x4), 6.7 waves.
// ---------------------------------------------------------------------------

#define BDIM   32
#define CIN    128
#define HH     64
#define WWID   64
#define COUT   256
#define HOUT   62
#define WOUT   62
#define PIX_PER_IMG (HOUT*WOUT)         // 3844

__device__ __half g_x[(size_t)BDIM * HH * WWID * CIN];   // NHWC fp16, 32 MB
__device__ __half g_w[9 * COUT * CIN];                   // (1-2W), [kp][co][cin]

static __device__ __forceinline__ uint32_t smem_u32(const void* p) {
    uint32_t a;
    asm("{ .reg .u64 t; cvta.to.shared.u64 t, %1; cvt.u32.u64 %0, t; }"
        : "=r"(a) : "l"(p));
    return a;
}

// ---------------------------------------------------------------------------
// Prep 1: x NCHW fp32 -> NHWC fp16
// ---------------------------------------------------------------------------
__global__ void x_to_nhwc(const float* __restrict__ x) {
    __shared__ float t[32][33];
    int bh = blockIdx.x;               // b*64 + h
    int b  = bh >> 6, h = bh & 63;
    int c0 = blockIdx.y * 32;
    int w0 = blockIdx.z * 32;
    int tx = threadIdx.x & 31, ty = threadIdx.x >> 5;

    const float* src = x + ((size_t)(b * CIN + c0)) * (HH * WWID) + h * WWID + w0;
#pragma unroll
    for (int i = 0; i < 4; i++)
        t[ty + 8 * i][tx] = src[(size_t)(ty + 8 * i) * (HH * WWID) + tx];
    __syncthreads();

    __half* dst = g_x + ((size_t)bh * WWID + w0) * CIN + c0;
#pragma unroll
    for (int i = 0; i < 4; i++)
        dst[(size_t)(ty + 8 * i) * CIN + tx] = __float2half_rn(t[tx][ty + 8 * i]);
}

// ---------------------------------------------------------------------------
// Prep 2: W -> g_w[kp][co][cin] = 1-2W (fp16)
// ---------------------------------------------------------------------------
__global__ void w_prep(const float* __restrict__ W) {
    int idx = blockIdx.x * 256 + threadIdx.x;
    if (idx < COUT * CIN * 9) {
        int co  = idx / (CIN * 9);
        int r   = idx - co * (CIN * 9);
        int cin = r / 9;
        int kp  = r - cin * 9;
        g_w[(kp * COUT + co) * CIN + cin] = __float2half_rn(1.0f - 2.0f * W[idx]);
    }
}

// ---------------------------------------------------------------------------
// Main: CTA = 256 co x 124 pixels (image b, output rows r0,r0+1).
// Patch = input rows r0..r0+3 (256 rows x 256B = 64KB), loaded once.
// A (weights) double-buffered over 9 kp. 16 warps: 4(M) x 4(N), warp 64x32.
// grid (31, 32), 512 threads.
// ---------------------------------------------------------------------------
#define ASTAGE 65536                  // per-kp A tile: 256 co x 256B
#define PATCH_OFF (2*32768*2)         // after 2 A stages (2*65536)
#define SMEM_BYTES (2*65536 + 65536 + 2048)

__global__ void __launch_bounds__(512, 1)
xorconv_main(float* __restrict__ out) {
    extern __shared__ char smem[];
    const uint32_t sb = smem_u32(smem);
    const uint32_t PB = sb + 2 * ASTAGE;        // patch base

    const int tid = threadIdx.x;
    const int l   = tid & 31;
    const int w   = tid >> 5;          // 0..15
    const int wm  = w & 3;             // M group (64 co)
    const int wn  = w >> 2;            // N group (32 pix)
    const int b   = blockIdx.y;
    const int r0  = blockIdx.x * 2;    // first output row

    // ----- cp.async mapping: thread = (chunk c, row-group rgrp)
    const int c    = tid & 15;         // 16B chunk in a 256B row
    const int rgrp = tid >> 4;         // 32 groups; rows r = rgrp + 32*i

    // Patch load: 256 contiguous g_x rows starting at (b, r0, 0)
    {
        const __half* xsrc = g_x + ((size_t)(b * (HH * WWID) + r0 * WWID)) * CIN;
#pragma unroll
        for (int i = 0; i < 8; i++) {
            int r = rgrp + 32 * i;
            uint32_t sw = (uint32_t)r * 256u + (uint32_t)((c ^ (r & 7)) * 16);
            asm volatile("cp.async.cg.shared.global [%0], [%1], 16;"
                         :: "r"(PB + sw), "l"(xsrc + (size_t)r * CIN + c * 8));
        }
    }

    auto load_A = [&](int s, int kp) {
        uint32_t dA = sb + s * ASTAGE;
        const __half* wp = g_w + kp * COUT * CIN;
#pragma unroll
        for (int i = 0; i < 8; i++) {
            int r = rgrp + 32 * i;
            uint32_t sw = (uint32_t)r * 256u + (uint32_t)((c ^ (r & 7)) * 16);
            asm volatile("cp.async.cg.shared.global [%0], [%1], 16;"
                         :: "r"(dA + sw), "l"(wp + r * CIN + c * 8));
        }
    };

    load_A(0, 0);
    asm volatile("cp.async.commit_group;" ::: "memory");   // G0 = patch + A0

    // ----- per-lane B patch-row offsets (clamped pad rows)
    const uint32_t selA = (uint32_t)(l >> 4);
    const uint32_t selB = (uint32_t)((l >> 3) & 1);
    const int rowA0 = wm * 64 + (l & 15);
    int pr0[2];
#pragma unroll
    for (int nb = 0; nb < 2; nb++) {
        int n = wn * 32 + (l & 7) + ((l >> 4) << 3) + nb * 16;
        if (n > 123) n = 123;
        pr0[nb] = (n / WOUT) * WWID + (n % WOUT);
    }

    float acc[4][4][4];
#pragma unroll
    for (int a = 0; a < 4; a++)
#pragma unroll
        for (int bb = 0; bb < 4; bb++)
#pragma unroll
            for (int e = 0; e < 4; e++) acc[a][bb][e] = 0.f;

    for (int kp = 0; kp < 9; kp++) {
        if (kp < 8) {
            load_A((kp + 1) & 1, kp + 1);
            asm volatile("cp.async.commit_group;" ::: "memory");
            asm volatile("cp.async.wait_group 1;" ::: "memory");
        } else {
            asm volatile("cp.async.wait_group 0;" ::: "memory");
        }
        __syncthreads();

        const uint32_t A = sb + (kp & 1) * ASTAGE;
        const int kh = kp / 3, kw = kp - 3 * kh;
        const int shift = kh * WWID + kw;
        uint32_t prow[2], pbase[2];
#pragma unroll
        for (int nb = 0; nb < 2; nb++) {
            prow[nb]  = (uint32_t)(pr0[nb] + shift);
            pbase[nb] = PB + prow[nb] * 256u;
        }

#pragma unroll
        for (int j = 0; j < 8; j++) {            // K=128 in 8 x k16
            uint32_t a[4][4], bq[2][4];
#pragma unroll
            for (int fm = 0; fm < 4; fm++) {
                int r = rowA0 + fm * 16;
                uint32_t ch = ((uint32_t)(2 * j) + selA) ^ (uint32_t)(r & 7);
                uint32_t ad = A + (uint32_t)r * 256u + ch * 16u;
                asm volatile(
                    "ldmatrix.sync.aligned.m8n8.x4.shared.b16 {%0,%1,%2,%3}, [%4];"
                    : "=r"(a[fm][0]), "=r"(a[fm][1]), "=r"(a[fm][2]), "=r"(a[fm][3])
                    : "r"(ad));
            }
#pragma unroll
            for (int nb = 0; nb < 2; nb++) {
                uint32_t ch = ((uint32_t)(2 * j) + selB) ^ (prow[nb] & 7u);
                uint32_t ad = pbase[nb] + ch * 16u;
                asm volatile(
                    "ldmatrix.sync.aligned.m8n8.x4.shared.b16 {%0,%1,%2,%3}, [%4];"
                    : "=r"(bq[nb][0]), "=r"(bq[nb][1]), "=r"(bq[nb][2]), "=r"(bq[nb][3])
                    : "r"(ad));
            }
#pragma unroll
            for (int fm = 0; fm < 4; fm++)
#pragma unroll
                for (int nf = 0; nf < 4; nf++) {
                    asm volatile(
                        "mma.sync.aligned.m16n8k16.row.col.f32.f16.f16.f32 "
                        "{%0,%1,%2,%3}, {%4,%5,%6,%7}, {%8,%9}, {%0,%1,%2,%3};"
                        : "+f"(acc[fm][nf][0]), "+f"(acc[fm][nf][1]),
                          "+f"(acc[fm][nf][2]), "+f"(acc[fm][nf][3])
                        : "r"(a[fm][0]), "r"(a[fm][1]), "r"(a[fm][2]), "r"(a[fm][3]),
                          "r"(bq[nf >> 1][(nf & 1) * 2]),
                          "r"(bq[nf >> 1][(nf & 1) * 2 + 1]));
                }
        }
        __syncthreads();   // stage fully consumed before next-next overwrite
    }

    // ----- epilogue: direct NCHW fp32 stores (skip pad pixels n>=124)
#pragma unroll
    for (int fm = 0; fm < 4; fm++) {
        int m = wm * 64 + fm * 16 + (l >> 2);
        size_t mb = (size_t)(b * COUT + m) * PIX_PER_IMG;
#pragma unroll
        for (int nf = 0; nf < 4; nf++) {
            int n0 = wn * 32 + nf * 8 + (l & 3) * 2;
#pragma unroll
            for (int e = 0; e < 2; e++) {
                int n = n0 + e;
                if (n < 124) {
                    int ho = r0 + (n >= WOUT ? 1 : 0);
                    int wo = n - (n >= WOUT ? WOUT : 0);
                    size_t idx = mb + (size_t)ho * WOUT + wo;
                    out[idx]                              = acc[fm][nf][e];
                    out[idx + (size_t)8 * PIX_PER_IMG]    = acc[fm][nf][2 + e];
                }
            }
        }
    }
}

// ---------------------------------------------------------------------------
extern "C" void kernel_launch(void* const* d_in, const int* in_sizes, int n_in,
                              void* d_out, int out_size) {
    const float* x = (const float*)d_in[0];
    const float* W = (const float*)d_in[1];
    float* out = (float*)d_out;

    dim3 gt(BDIM * HH, CIN / 32, WWID / 32);
    x_to_nhwc<<<gt, 256>>>(x);
    w_prep<<<(COUT * CIN * 9 + 255) / 256, 256>>>(W);

    cudaFuncSetAttribute(xorconv_main,
                         cudaFuncAttributeMaxDynamicSharedMemorySize, SMEM_BYTES);
    dim3 gm(HOUT / 2, BDIM);   // 31 row-pairs x 32 images
    xorconv_main<<<gm, 512, SMEM_BYTES>>>(out);
}

// round 6
// speedup vs baseline: 1.6366x; 1.0437x over previous
#include <cuda_runtime.h>
#include <cuda_fp16.h>
#include <cstdint>

// ---------------------------------------------------------------------------
// XORConv2d: out = conv_valid(x, 1-2W), x (32,128,64,64) f32, W (256,128,3,3)
// Implicit GEMM on mma.sync fp16/fp32. sm_103 plain target (no tcgen05).
// R5 resubmit (prior round was an infra failure, kernel never ran):
// single __syncthreads per kp; full-sector writes in the NHWC prep kernel.
// ---------------------------------------------------------------------------

#define BDIM   32
#define CIN    128
#define HH     64
#define WWID   64
#define COUT   256
#define HOUT   62
#define WOUT   62
#define PIX_PER_IMG (HOUT*WOUT)         // 3844

__device__ __half g_x[(size_t)BDIM * HH * WWID * CIN];   // NHWC fp16, 32 MB
__device__ __half g_w[9 * COUT * CIN];                   // (1-2W), [kp][co][cin]

static __device__ __forceinline__ uint32_t smem_u32(const void* p) {
    uint32_t a;
    asm("{ .reg .u64 t; cvta.to.shared.u64 t, %1; cvt.u32.u64 %0, t; }"
        : "=r"(a) : "l"(p));
    return a;
}

// ---------------------------------------------------------------------------
// Prep 1: x NCHW fp32 -> NHWC fp16. 64(c) x 32(w) tiles; packed half2 writes
// so every warp store is a full 128B sector. grid (2048, 2, 2), 256 thr.
// ---------------------------------------------------------------------------
__global__ void x_to_nhwc(const float* __restrict__ x) {
    __shared__ float t[64][33];
    int bh = blockIdx.x;               // b*64 + h
    int b  = bh >> 6, h = bh & 63;
    int c0 = blockIdx.y * 64;
    int w0 = blockIdx.z * 32;
    int l  = threadIdx.x & 31, wy = threadIdx.x >> 5;   // 8 warps

    const float* src = x + ((size_t)(b * CIN + c0)) * (HH * WWID) + h * WWID + w0;
#pragma unroll
    for (int i = 0; i < 8; i++)
        t[wy + 8 * i][l] = src[(size_t)(wy + 8 * i) * (HH * WWID) + l];
    __syncthreads();

#pragma unroll
    for (int i = 0; i < 4; i++) {
        int ww = wy + 8 * i;
        __half2 v = __floats2half2_rn(t[2 * l][ww], t[2 * l + 1][ww]);
        __half* drow = g_x + ((size_t)(bh * WWID) + w0 + ww) * CIN + c0;
        ((uint32_t*)drow)[l] = *(uint32_t*)&v;
    }
}

// ---------------------------------------------------------------------------
// Prep 2: W -> g_w[kp][co][cin] = 1-2W (fp16)
// ---------------------------------------------------------------------------
__global__ void w_prep(const float* __restrict__ W) {
    int idx = blockIdx.x * 256 + threadIdx.x;
    if (idx < COUT * CIN * 9) {
        int co  = idx / (CIN * 9);
        int r   = idx - co * (CIN * 9);
        int cin = r / 9;
        int kp  = r - cin * 9;
        g_w[(kp * COUT + co) * CIN + cin] = __float2half_rn(1.0f - 2.0f * W[idx]);
    }
}

// ---------------------------------------------------------------------------
// Main: CTA = 256 co x 124 pixels (image b, output rows r0,r0+1).
// Patch = input rows r0..r0+3 (256 rows x 256B = 64KB), loaded once.
// A (weights) double-buffered over 9 kp, ONE barrier per kp.
// 16 warps: 4(M) x 4(N), warp tile 64x32. grid (31, 32), 512 threads.
// ---------------------------------------------------------------------------
#define ASTAGE 65536
#define SMEM_BYTES (2*65536 + 65536 + 2048)

__global__ void __launch_bounds__(512, 1)
xorconv_main(float* __restrict__ out) {
    extern __shared__ char smem[];
    const uint32_t sb = smem_u32(smem);
    const uint32_t PB = sb + 2 * ASTAGE;        // patch base

    const int tid = threadIdx.x;
    const int l   = tid & 31;
    const int w   = tid >> 5;          // 0..15
    const int wm  = w & 3;             // M group (64 co)
    const int wn  = w >> 2;            // N group (32 pix)
    const int b   = blockIdx.y;
    const int r0  = blockIdx.x * 2;    // first output row

    const int c    = tid & 15;         // 16B chunk in a 256B row
    const int rgrp = tid >> 4;         // 32 groups; rows r = rgrp + 32*i

    // Patch: 256 contiguous g_x rows starting at (b, r0, 0)
    {
        const __half* xsrc = g_x + ((size_t)(b * (HH * WWID) + r0 * WWID)) * CIN;
#pragma unroll
        for (int i = 0; i < 8; i++) {
            int r = rgrp + 32 * i;
            uint32_t sw = (uint32_t)r * 256u + (uint32_t)((c ^ (r & 7)) * 16);
            asm volatile("cp.async.cg.shared.global [%0], [%1], 16;"
                         :: "r"(PB + sw), "l"(xsrc + (size_t)r * CIN + c * 8));
        }
    }

    auto load_A = [&](int s, int kp) {
        uint32_t dA = sb + s * ASTAGE;
        const __half* wp = g_w + kp * COUT * CIN;
#pragma unroll
        for (int i = 0; i < 8; i++) {
            int r = rgrp + 32 * i;
            uint32_t sw = (uint32_t)r * 256u + (uint32_t)((c ^ (r & 7)) * 16);
            asm volatile("cp.async.cg.shared.global [%0], [%1], 16;"
                         :: "r"(dA + sw), "l"(wp + r * CIN + c * 8));
        }
        asm volatile("cp.async.commit_group;" ::: "memory");
    };

    load_A(0, 0);   // one group: patch + A0

    const uint32_t selA = (uint32_t)(l >> 4);
    const uint32_t selB = (uint32_t)((l >> 3) & 1);
    const int rowA0 = wm * 64 + (l & 15);
    int pr0[2];
#pragma unroll
    for (int nb = 0; nb < 2; nb++) {
        int n = wn * 32 + (l & 7) + ((l >> 4) << 3) + nb * 16;
        if (n > 123) n = 123;
        pr0[nb] = (n / WOUT) * WWID + (n % WOUT);
    }

    float acc[4][4][4];
#pragma unroll
    for (int a = 0; a < 4; a++)
#pragma unroll
        for (int bb = 0; bb < 4; bb++)
#pragma unroll
            for (int e = 0; e < 4; e++) acc[a][bb][e] = 0.f;

    for (int kp = 0; kp < 9; kp++) {
        // A(kp) (and patch, first iter) must be resident; all warps must have
        // finished reading the stage A(kp+1) will overwrite (previous iter's
        // compute ended before this barrier).
        asm volatile("cp.async.wait_group 0;" ::: "memory");
        __syncthreads();
        if (kp < 8) load_A((kp + 1) & 1, kp + 1);   // overlaps compute below

        const uint32_t A = sb + (kp & 1) * ASTAGE;
        const int kh = kp / 3, kw = kp - 3 * kh;
        const int shift = kh * WWID + kw;
        uint32_t prow[2], pbase[2];
#pragma unroll
        for (int nb = 0; nb < 2; nb++) {
            prow[nb]  = (uint32_t)(pr0[nb] + shift);
            pbase[nb] = PB + prow[nb] * 256u;
        }

#pragma unroll
        for (int j = 0; j < 8; j++) {            // K=128 in 8 x k16
            uint32_t a[4][4], bq[2][4];
#pragma unroll
            for (int fm = 0; fm < 4; fm++) {
                int r = rowA0 + fm * 16;
                uint32_t ch = ((uint32_t)(2 * j) + selA) ^ (uint32_t)(r & 7);
                uint32_t ad = A + (uint32_t)r * 256u + ch * 16u;
                asm volatile(
                    "ldmatrix.sync.aligned.m8n8.x4.shared.b16 {%0,%1,%2,%3}, [%4];"
                    : "=r"(a[fm][0]), "=r"(a[fm][1]), "=r"(a[fm][2]), "=r"(a[fm][3])
                    : "r"(ad));
            }
#pragma unroll
            for (int nb = 0; nb < 2; nb++) {
                uint32_t ch = ((uint32_t)(2 * j) + selB) ^ (prow[nb] & 7u);
                uint32_t ad = pbase[nb] + ch * 16u;
                asm volatile(
                    "ldmatrix.sync.aligned.m8n8.x4.shared.b16 {%0,%1,%2,%3}, [%4];"
                    : "=r"(bq[nb][0]), "=r"(bq[nb][1]), "=r"(bq[nb][2]), "=r"(bq[nb][3])
                    : "r"(ad));
            }
#pragma unroll
            for (int fm = 0; fm < 4; fm++)
#pragma unroll
                for (int nf = 0; nf < 4; nf++) {
                    asm volatile(
                        "mma.sync.aligned.m16n8k16.row.col.f32.f16.f16.f32 "
                        "{%0,%1,%2,%3}, {%4,%5,%6,%7}, {%8,%9}, {%0,%1,%2,%3};"
                        : "+f"(acc[fm][nf][0]), "+f"(acc[fm][nf][1]),
                          "+f"(acc[fm][nf][2]), "+f"(acc[fm][nf][3])
                        : "r"(a[fm][0]), "r"(a[fm][1]), "r"(a[fm][2]), "r"(a[fm][3]),
                          "r"(bq[nf >> 1][(nf & 1) * 2]),
                          "r"(bq[nf >> 1][(nf & 1) * 2 + 1]));
                }
        }
    }

    // ----- epilogue: direct NCHW fp32 stores (skip pad pixels n>=124)
#pragma unroll
    for (int fm = 0; fm < 4; fm++) {
        int m = wm * 64 + fm * 16 + (l >> 2);
        size_t mb = (size_t)(b * COUT + m) * PIX_PER_IMG;
#pragma unroll
        for (int nf = 0; nf < 4; nf++) {
            int n0 = wn * 32 + nf * 8 + (l & 3) * 2;
#pragma unroll
            for (int e = 0; e < 2; e++) {
                int n = n0 + e;
                if (n < 124) {
                    int ho = r0 + (n >= WOUT ? 1 : 0);
                    int wo = n - (n >= WOUT ? WOUT : 0);
                    size_t idx = mb + (size_t)ho * WOUT + wo;
                    out[idx]                              = acc[fm][nf][e];
                    out[idx + (size_t)8 * PIX_PER_IMG]    = acc[fm][nf][2 + e];
                }
            }
        }
    }
}

// ---------------------------------------------------------------------------
extern "C" void kernel_launch(void* const* d_in, const int* in_sizes, int n_in,
                              void* d_out, int out_size) {
    const float* x = (const float*)d_in[0];
    const float* W = (const float*)d_in[1];
    float* out = (float*)d_out;

    dim3 gt(BDIM * HH, CIN / 64, WWID / 32);
    x_to_nhwc<<<gt, 256>>>(x);
    w_prep<<<(COUT * CIN * 9 + 255) / 256, 256>>>(W);

    cudaFuncSetAttribute(xorconv_main,
                         cudaFuncAttributeMaxDynamicSharedMemorySize, SMEM_BYTES);
    dim3 gm(HOUT / 2, BDIM);   // 31 row-pairs x 32 images
    xorconv_main<<<gm, 512, SMEM_BYTES>>>(out);
}

// round 7
// speedup vs baseline: 1.6747x; 1.0233x over previous
#include <cuda_runtime.h>
#include <cuda_fp16.h>
#include <cstdint>

// ---------------------------------------------------------------------------
// XORConv2d: out = conv_valid(x, 1-2W), x (32,128,64,64) f32, W (256,128,3,3)
// Implicit GEMM on mma.sync fp16/fp32. sm_103 plain target (no tcgen05).
// R7: register double-buffered ldmatrix fragments (load j+1 during mma of j)
// to hide LSU->HMMA dependency latency. Everything else as R6.
// ---------------------------------------------------------------------------

#define BDIM   32
#define CIN    128
#define HH     64
#define WWID   64
#define COUT   256
#define HOUT   62
#define WOUT   62
#define PIX_PER_IMG (HOUT*WOUT)         // 3844

__device__ __half g_x[(size_t)BDIM * HH * WWID * CIN];   // NHWC fp16, 32 MB
__device__ __half g_w[9 * COUT * CIN];                   // (1-2W), [kp][co][cin]

static __device__ __forceinline__ uint32_t smem_u32(const void* p) {
    uint32_t a;
    asm("{ .reg .u64 t; cvta.to.shared.u64 t, %1; cvt.u32.u64 %0, t; }"
        : "=r"(a) : "l"(p));
    return a;
}

// ---------------------------------------------------------------------------
// Prep 1: x NCHW fp32 -> NHWC fp16 (full-sector packed half2 writes)
// ---------------------------------------------------------------------------
__global__ void x_to_nhwc(const float* __restrict__ x) {
    __shared__ float t[64][33];
    int bh = blockIdx.x;               // b*64 + h
    int b  = bh >> 6, h = bh & 63;
    int c0 = blockIdx.y * 64;
    int w0 = blockIdx.z * 32;
    int l  = threadIdx.x & 31, wy = threadIdx.x >> 5;   // 8 warps

    const float* src = x + ((size_t)(b * CIN + c0)) * (HH * WWID) + h * WWID + w0;
#pragma unroll
    for (int i = 0; i < 8; i++)
        t[wy + 8 * i][l] = src[(size_t)(wy + 8 * i) * (HH * WWID) + l];
    __syncthreads();

#pragma unroll
    for (int i = 0; i < 4; i++) {
        int ww = wy + 8 * i;
        __half2 v = __floats2half2_rn(t[2 * l][ww], t[2 * l + 1][ww]);
        __half* drow = g_x + ((size_t)(bh * WWID) + w0 + ww) * CIN + c0;
        ((uint32_t*)drow)[l] = *(uint32_t*)&v;
    }
}

// ---------------------------------------------------------------------------
// Prep 2: W -> g_w[kp][co][cin] = 1-2W (fp16)
// ---------------------------------------------------------------------------
__global__ void w_prep(const float* __restrict__ W) {
    int idx = blockIdx.x * 256 + threadIdx.x;
    if (idx < COUT * CIN * 9) {
        int co  = idx / (CIN * 9);
        int r   = idx - co * (CIN * 9);
        int cin = r / 9;
        int kp  = r - cin * 9;
        g_w[(kp * COUT + co) * CIN + cin] = __float2half_rn(1.0f - 2.0f * W[idx]);
    }
}

// ---------------------------------------------------------------------------
// Main: CTA = 256 co x 124 pixels. Patch (64KB) loaded once; A double-buffered
// over 9 kp, one barrier per kp; fragments double-buffered over j.
// 16 warps: 4(M) x 4(N), warp tile 64x32. grid (31, 32), 512 threads.
// ---------------------------------------------------------------------------
#define ASTAGE 65536
#define SMEM_BYTES (2*65536 + 65536 + 2048)

__global__ void __launch_bounds__(512, 1)
xorconv_main(float* __restrict__ out) {
    extern __shared__ char smem[];
    const uint32_t sb = smem_u32(smem);
    const uint32_t PB = sb + 2 * ASTAGE;        // patch base

    const int tid = threadIdx.x;
    const int l   = tid & 31;
    const int w   = tid >> 5;          // 0..15
    const int wm  = w & 3;             // M group (64 co)
    const int wn  = w >> 2;            // N group (32 pix)
    const int b   = blockIdx.y;
    const int r0  = blockIdx.x * 2;    // first output row

    const int c    = tid & 15;         // 16B chunk in a 256B row
    const int rgrp = tid >> 4;         // 32 groups; rows r = rgrp + 32*i

    // Patch: 256 contiguous g_x rows starting at (b, r0, 0)
    {
        const __half* xsrc = g_x + ((size_t)(b * (HH * WWID) + r0 * WWID)) * CIN;
#pragma unroll
        for (int i = 0; i < 8; i++) {
            int r = rgrp + 32 * i;
            uint32_t sw = (uint32_t)r * 256u + (uint32_t)((c ^ (r & 7)) * 16);
            asm volatile("cp.async.cg.shared.global [%0], [%1], 16;"
                         :: "r"(PB + sw), "l"(xsrc + (size_t)r * CIN + c * 8));
        }
    }

    auto load_A = [&](int s, int kp) {
        uint32_t dA = sb + s * ASTAGE;
        const __half* wp = g_w + kp * COUT * CIN;
#pragma unroll
        for (int i = 0; i < 8; i++) {
            int r = rgrp + 32 * i;
            uint32_t sw = (uint32_t)r * 256u + (uint32_t)((c ^ (r & 7)) * 16);
            asm volatile("cp.async.cg.shared.global [%0], [%1], 16;"
                         :: "r"(dA + sw), "l"(wp + r * CIN + c * 8));
        }
        asm volatile("cp.async.commit_group;" ::: "memory");
    };

    load_A(0, 0);   // one group: patch + A0

    const uint32_t selA = (uint32_t)(l >> 4);
    const uint32_t selB = (uint32_t)((l >> 3) & 1);
    const int rowA0 = wm * 64 + (l & 15);
    int pr0[2];
#pragma unroll
    for (int nb = 0; nb < 2; nb++) {
        int n = wn * 32 + (l & 7) + ((l >> 4) << 3) + nb * 16;
        if (n > 123) n = 123;
        pr0[nb] = (n / WOUT) * WWID + (n % WOUT);
    }

    float acc[4][4][4];
#pragma unroll
    for (int a = 0; a < 4; a++)
#pragma unroll
        for (int bb = 0; bb < 4; bb++)
#pragma unroll
            for (int e = 0; e < 4; e++) acc[a][bb][e] = 0.f;

    uint32_t afr[2][4][4], bfr[2][2][4];

    for (int kp = 0; kp < 9; kp++) {
        asm volatile("cp.async.wait_group 0;" ::: "memory");
        __syncthreads();
        if (kp < 8) load_A((kp + 1) & 1, kp + 1);   // overlaps compute below

        const uint32_t A = sb + (kp & 1) * ASTAGE;
        const int kh = kp / 3, kw = kp - 3 * kh;
        const int shift = kh * WWID + kw;
        uint32_t prow[2], pbase[2];
#pragma unroll
        for (int nb = 0; nb < 2; nb++) {
            prow[nb]  = (uint32_t)(pr0[nb] + shift);
            pbase[nb] = PB + prow[nb] * 256u;
        }

        // fragment loader for K-step j into buffer p
        auto load_frags = [&](int j, int p) {
#pragma unroll
            for (int fm = 0; fm < 4; fm++) {
                int r = rowA0 + fm * 16;
                uint32_t ch = ((uint32_t)(2 * j) + selA) ^ (uint32_t)(r & 7);
                uint32_t ad = A + (uint32_t)r * 256u + ch * 16u;
                asm volatile(
                    "ldmatrix.sync.aligned.m8n8.x4.shared.b16 {%0,%1,%2,%3}, [%4];"
                    : "=r"(afr[p][fm][0]), "=r"(afr[p][fm][1]),
                      "=r"(afr[p][fm][2]), "=r"(afr[p][fm][3])
                    : "r"(ad));
            }
#pragma unroll
            for (int nb = 0; nb < 2; nb++) {
                uint32_t ch = ((uint32_t)(2 * j) + selB) ^ (prow[nb] & 7u);
                uint32_t ad = pbase[nb] + ch * 16u;
                asm volatile(
                    "ldmatrix.sync.aligned.m8n8.x4.shared.b16 {%0,%1,%2,%3}, [%4];"
                    : "=r"(bfr[p][nb][0]), "=r"(bfr[p][nb][1]),
                      "=r"(bfr[p][nb][2]), "=r"(bfr[p][nb][3])
                    : "r"(ad));
            }
        };

        load_frags(0, 0);
#pragma unroll
        for (int j = 0; j < 8; j++) {            // K=128 in 8 x k16
            const int p = j & 1;
            if (j < 7) load_frags(j + 1, p ^ 1); // prefetch next step's frags
#pragma unroll
            for (int fm = 0; fm < 4; fm++)
#pragma unroll
                for (int nf = 0; nf < 4; nf++) {
                    asm volatile(
                        "mma.sync.aligned.m16n8k16.row.col.f32.f16.f16.f32 "
                        "{%0,%1,%2,%3}, {%4,%5,%6,%7}, {%8,%9}, {%0,%1,%2,%3};"
                        : "+f"(acc[fm][nf][0]), "+f"(acc[fm][nf][1]),
                          "+f"(acc[fm][nf][2]), "+f"(acc[fm][nf][3])
                        : "r"(afr[p][fm][0]), "r"(afr[p][fm][1]),
                          "r"(afr[p][fm][2]), "r"(afr[p][fm][3]),
                          "r"(bfr[p][nf >> 1][(nf & 1) * 2]),
                          "r"(bfr[p][nf >> 1][(nf & 1) * 2 + 1]));
                }
        }
    }

    // ----- epilogue: direct NCHW fp32 stores (skip pad pixels n>=124)
#pragma unroll
    for (int fm = 0; fm < 4; fm++) {
        int m = wm * 64 + fm * 16 + (l >> 2);
        size_t mb = (size_t)(b * COUT + m) * PIX_PER_IMG;
#pragma unroll
        for (int nf = 0; nf < 4; nf++) {
            int n0 = wn * 32 + nf * 8 + (l & 3) * 2;
#pragma unroll
            for (int e = 0; e < 2; e++) {
                int n = n0 + e;
                if (n < 124) {
                    int ho = r0 + (n >= WOUT ? 1 : 0);
                    int wo = n - (n >= WOUT ? WOUT : 0);
                    size_t idx = mb + (size_t)ho * WOUT + wo;
                    out[idx]                              = acc[fm][nf][e];
                    out[idx + (size_t)8 * PIX_PER_IMG]    = acc[fm][nf][2 + e];
                }
            }
        }
    }
}

// ---------------------------------------------------------------------------
extern "C" void kernel_launch(void* const* d_in, const int* in_sizes, int n_in,
                              void* d_out, int out_size) {
    const float* x = (const float*)d_in[0];
    const float* W = (const float*)d_in[1];
    float* out = (float*)d_out;

    dim3 gt(BDIM * HH, CIN / 64, WWID / 32);
    x_to_nhwc<<<gt, 256>>>(x);
    w_prep<<<(COUT * CIN * 9 + 255) / 256, 256>>>(W);

    cudaFuncSetAttribute(xorconv_main,
                         cudaFuncAttributeMaxDynamicSharedMemorySize, SMEM_BYTES);
    dim3 gm(HOUT / 2, BDIM);   // 31 row-pairs x 32 images
    xorconv_main<<<gm, 512, SMEM_BYTES>>>(out);
}